// round 1
// baseline (speedup 1.0000x reference)
#include <cuda_runtime.h>
#include <math.h>

#define BB 4
#define SS 2048
#define DD 1024
#define HH 16
#define HD 64
#define MM (BB * SS)   // 8192

// Scratch: q,k,v in [B,H,S,HD], attn in [B,S,D]
__device__ float g_q[BB * HH * SS * HD];
__device__ float g_k[BB * HH * SS * HD];
__device__ float g_v[BB * HH * SS * HD];
__device__ float g_attn[BB * SS * DD];

// ---------------------------------------------------------------------------
// Projection GEMM: Y[M,N] = X[M,K] @ W[N,K]^T + bias[N]
// BM=128, BN=128, BK=8, 256 threads, 8x8 microtile.
// osel: 0->g_q, 1->g_k, 2->g_v, 3->out_ext ([B,S,D] plain layout)
// xsel: 0->Xp param, 1->g_attn
// head_layout: scatter N into (h, hd) and write [B,H,S,HD]
// ---------------------------------------------------------------------------
__global__ __launch_bounds__(256)
void proj_kernel(const float* __restrict__ Xp,
                 const float* __restrict__ W,
                 const float* __restrict__ bias,
                 float* out_ext, int xsel, int osel, int head_layout)
{
    __shared__ float As[8][132];
    __shared__ float Bs[8][132];

    const float* X = (xsel == 1) ? g_attn : Xp;
    float* out = (osel == 0) ? g_q : (osel == 1) ? g_k : (osel == 2) ? g_v : out_ext;

    const int m0 = blockIdx.y * 128;
    const int n0 = blockIdx.x * 128;
    const int tid = threadIdx.x;
    const int tx = tid & 15;        // 0..15 -> col group
    const int ty = tid >> 4;        // 0..15 -> row group

    const int lrow = tid >> 1;          // 0..127
    const int lcol = (tid & 1) * 4;     // 0 or 4

    float c[8][8];
#pragma unroll
    for (int i = 0; i < 8; i++)
#pragma unroll
        for (int j = 0; j < 8; j++) c[i][j] = 0.f;

    for (int k0 = 0; k0 < DD; k0 += 8) {
        float4 av = *(const float4*)&X[(size_t)(m0 + lrow) * DD + k0 + lcol];
        float4 bv = *(const float4*)&W[(size_t)(n0 + lrow) * DD + k0 + lcol];
        As[lcol + 0][lrow] = av.x;
        As[lcol + 1][lrow] = av.y;
        As[lcol + 2][lrow] = av.z;
        As[lcol + 3][lrow] = av.w;
        Bs[lcol + 0][lrow] = bv.x;
        Bs[lcol + 1][lrow] = bv.y;
        Bs[lcol + 2][lrow] = bv.z;
        Bs[lcol + 3][lrow] = bv.w;
        __syncthreads();

#pragma unroll
        for (int kk = 0; kk < 8; kk++) {
            float a[8], b[8];
            *(float4*)&a[0] = *(const float4*)&As[kk][ty * 8];
            *(float4*)&a[4] = *(const float4*)&As[kk][ty * 8 + 4];
            *(float4*)&b[0] = *(const float4*)&Bs[kk][tx * 8];
            *(float4*)&b[4] = *(const float4*)&Bs[kk][tx * 8 + 4];
#pragma unroll
            for (int i = 0; i < 8; i++)
#pragma unroll
                for (int j = 0; j < 8; j++)
                    c[i][j] = fmaf(a[i], b[j], c[i][j]);
        }
        __syncthreads();
    }

    // Epilogue
#pragma unroll
    for (int i = 0; i < 8; i++) {
        const int m = m0 + ty * 8 + i;
        const int bb = m / SS;
        const int ss = m - bb * SS;
        if (head_layout) {
            const int n = n0 + tx * 8;        // 8 consecutive n, HD=64 so same head
            const int h = n / HD;
            const int hd = n - h * HD;
            float* dst = &out[(((size_t)bb * HH + h) * SS + ss) * HD + hd];
#pragma unroll
            for (int j = 0; j < 8; j++)
                dst[j] = c[i][j] + bias[n + j];
        } else {
            float* dst = &out[(size_t)m * DD + n0 + tx * 8];
#pragma unroll
            for (int j = 0; j < 8; j++)
                dst[j] = c[i][j] + bias[n0 + tx * 8 + j];
        }
    }
}

// ---------------------------------------------------------------------------
// Flash attention (fp32). Block = (b, h, 64-row Q tile), 128 threads.
// Thread t handles row r = t/2, half = t&1 (32 of the 64 HD dims).
// Online softmax over 16-key sub-chunks; K/V staged in 64-row smem chunks.
// Writes O/l into g_attn laid out [B,S,D].
// ---------------------------------------------------------------------------
__global__ __launch_bounds__(128)
void attn_kernel()
{
    __shared__ float Qs[64][64];
    __shared__ float Ks[64][64];
    __shared__ float Vs[64][64];

    const int qt = blockIdx.x;   // 0..31
    const int h  = blockIdx.y;   // 0..15
    const int b  = blockIdx.z;   // 0..3
    const int tid = threadIdx.x;

    const size_t base = ((size_t)(b * HH + h)) * SS * HD;
    const float scale = 0.125f;  // 1/sqrt(64)

    // Load Q tile (4096 floats, 128 thr * 8 float4)
    for (int i = tid; i < 64 * 16; i += 128) {
        const int row = i >> 4;
        const int c4 = (i & 15) * 4;
        *(float4*)&Qs[row][c4] = *(const float4*)&g_q[base + (size_t)(qt * 64 + row) * HD + c4];
    }
    __syncthreads();

    const int r = tid >> 1;
    const int half = (tid & 1) * 32;

    float q[32];
#pragma unroll
    for (int d = 0; d < 32; d++) q[d] = Qs[r][half + d] * scale;

    float o[32];
#pragma unroll
    for (int d = 0; d < 32; d++) o[d] = 0.f;

    float mval = -1e30f, l = 0.f;

    for (int kc = 0; kc < SS; kc += 64) {
        __syncthreads();  // previous chunk consumed
        for (int i = tid; i < 64 * 16; i += 128) {
            const int row = i >> 4;
            const int c4 = (i & 15) * 4;
            *(float4*)&Ks[row][c4] = *(const float4*)&g_k[base + (size_t)(kc + row) * HD + c4];
            *(float4*)&Vs[row][c4] = *(const float4*)&g_v[base + (size_t)(kc + row) * HD + c4];
        }
        __syncthreads();

#pragma unroll 1
        for (int sub = 0; sub < 4; sub++) {
            float sc[16];
#pragma unroll
            for (int j = 0; j < 16; j++) {
                const float* kr = &Ks[sub * 16 + j][half];
                float s = 0.f;
#pragma unroll
                for (int d = 0; d < 32; d++) s = fmaf(q[d], kr[d], s);
                s += __shfl_xor_sync(0xffffffffu, s, 1);
                sc[j] = s;
            }
            float mc = sc[0];
#pragma unroll
            for (int j = 1; j < 16; j++) mc = fmaxf(mc, sc[j]);
            const float mnew = fmaxf(mval, mc);
            const float alpha = __expf(mval - mnew);
            float psum = 0.f;
#pragma unroll
            for (int j = 0; j < 16; j++) {
                sc[j] = __expf(sc[j] - mnew);
                psum += sc[j];
            }
            l = l * alpha + psum;
            mval = mnew;
#pragma unroll
            for (int d = 0; d < 32; d++) o[d] *= alpha;
#pragma unroll
            for (int j = 0; j < 16; j++) {
                const float* vr = &Vs[sub * 16 + j][half];
                const float p = sc[j];
#pragma unroll
                for (int d = 0; d < 32; d++) o[d] = fmaf(p, vr[d], o[d]);
            }
        }
    }

    const float inv = 1.f / l;
    float* orow = &g_attn[((size_t)(b * SS) + qt * 64 + r) * DD + h * HD + half];
#pragma unroll
    for (int d = 0; d < 32; d += 4) {
        float4 v4 = make_float4(o[d] * inv, o[d + 1] * inv, o[d + 2] * inv, o[d + 3] * inv);
        *(float4*)&orow[d] = v4;
    }
}

// ---------------------------------------------------------------------------
extern "C" void kernel_launch(void* const* d_in, const int* in_sizes, int n_in,
                              void* d_out, int out_size)
{
    const float* query = (const float*)d_in[0];
    const float* key   = (const float*)d_in[1];
    const float* value = (const float*)d_in[2];
    const float* Wq = (const float*)d_in[3];
    const float* bq = (const float*)d_in[4];
    const float* Wk = (const float*)d_in[5];
    const float* bk = (const float*)d_in[6];
    const float* Wv = (const float*)d_in[7];
    const float* bv = (const float*)d_in[8];
    const float* Wo = (const float*)d_in[9];
    const float* bo = (const float*)d_in[10];
    float* out = (float*)d_out;

    dim3 gblk(256);
    dim3 ggrid(DD / 128, MM / 128);   // (8, 64)

    // Q, K, V projections -> [B,H,S,HD]
    proj_kernel<<<ggrid, gblk>>>(query, Wq, bq, nullptr, 0, 0, 1);
    proj_kernel<<<ggrid, gblk>>>(key,   Wk, bk, nullptr, 0, 1, 1);
    proj_kernel<<<ggrid, gblk>>>(value, Wv, bv, nullptr, 0, 2, 1);

    // Attention -> g_attn [B,S,D]
    dim3 agrid(SS / 64, HH, BB);      // (32, 16, 4)
    attn_kernel<<<agrid, 128>>>();

    // Output projection: g_attn @ Wo^T + bo -> d_out [B,S,D]
    proj_kernel<<<ggrid, gblk>>>(nullptr, Wo, bo, out, 1, 3, 0);
}

// round 3
// speedup vs baseline: 2.1360x; 2.1360x over previous
#include <cuda_runtime.h>
#include <cuda_bf16.h>
#include <stdint.h>

#define BBATCH 4
#define SEQ 2048
#define DIM 1024
#define NHEAD 16
#define HDIM 64
#define MROWS (BBATCH * SEQ)   // 8192

// Scratch (device globals; no allocation)
__device__ float g_qT[BBATCH * NHEAD * HDIM * SEQ];  // [B,H,HD,S]
__device__ float g_kT[BBATCH * NHEAD * HDIM * SEQ];  // [B,H,HD,S]
__device__ float g_v [BBATCH * NHEAD * SEQ * HDIM];  // [B,H,S,HD]
__device__ float g_at[BBATCH * SEQ * DIM];           // [B,S,D]

// ---------------------------------------------------------------------------
__device__ __forceinline__ uint32_t s2u(const void* p) {
    uint32_t a;
    asm("{ .reg .u64 t; cvta.to.shared.u64 t, %1; cvt.u32.u64 %0, t; }" : "=r"(a) : "l"(p));
    return a;
}

#define LDSM4(r0, r1, r2, r3, a) \
    asm volatile("ldmatrix.sync.aligned.m8n8.x4.shared.b16 {%0,%1,%2,%3}, [%4];" \
                 : "=r"(r0), "=r"(r1), "=r"(r2), "=r"(r3) : "r"(a))

#define MMA16816(d, a0, a1, a2, a3, b0, b1) \
    asm volatile("mma.sync.aligned.m16n8k16.row.col.f32.bf16.bf16.f32 " \
                 "{%0,%1,%2,%3},{%4,%5,%6,%7},{%8,%9},{%0,%1,%2,%3};" \
                 : "+f"((d)[0]), "+f"((d)[1]), "+f"((d)[2]), "+f"((d)[3]) \
                 : "r"(a0), "r"(a1), "r"(a2), "r"(a3), "r"(b0), "r"(b1))

// split fp32 -> (hi bf16, lo bf16) pairs packed as uint2 (4 elems each)
__device__ __forceinline__ void split4(float4 v, uint2& hi, uint2& lo) {
    __nv_bfloat16 h0 = __float2bfloat16_rn(v.x);
    __nv_bfloat16 h1 = __float2bfloat16_rn(v.y);
    __nv_bfloat16 h2 = __float2bfloat16_rn(v.z);
    __nv_bfloat16 h3 = __float2bfloat16_rn(v.w);
    float l0 = v.x - __bfloat162float(h0);
    float l1 = v.y - __bfloat162float(h1);
    float l2 = v.z - __bfloat162float(h2);
    float l3 = v.w - __bfloat162float(h3);
    __nv_bfloat162 H01 = __halves2bfloat162(h0, h1);
    __nv_bfloat162 H23 = __halves2bfloat162(h2, h3);
    __nv_bfloat162 L01 = __floats2bfloat162_rn(l0, l1);
    __nv_bfloat162 L23 = __floats2bfloat162_rn(l2, l3);
    hi = make_uint2(*reinterpret_cast<uint32_t*>(&H01), *reinterpret_cast<uint32_t*>(&H23));
    lo = make_uint2(*reinterpret_cast<uint32_t*>(&L01), *reinterpret_cast<uint32_t*>(&L23));
}

// ---------------------------------------------------------------------------
// mma.sync projection GEMM: Y[8192,1024] = X @ W^T + bias
// Tile 128x128, BK=64, 8 warps (warp tile 64x32), bf16 split (3 MMAs).
// mode: 0 -> plain [M,N]; 1 -> [B,H,S,HD]; 2 -> transposed [B,H,HD,S]
// smem rows: 64 bf16 = 128B, XOR-swizzled in 16B chunks by (row&7).
// ---------------------------------------------------------------------------
#define SM_AH 0
#define SM_AL 16384
#define SM_BH 32768
#define SM_BL 49152
#define PROJ_SMEM 65536

__global__ __launch_bounds__(256, 2)
void proj_mma(const float* __restrict__ X, const float* __restrict__ W,
              const float* __restrict__ bias, float* __restrict__ out, int mode)
{
    extern __shared__ __align__(128) char smc[];
    const uint32_t sb = s2u(smc);
    const int tid = threadIdx.x;
    const int wid = tid >> 5;
    const int lane = tid & 31;

    const int m0 = blockIdx.y * 128;
    const int n0 = blockIdx.x * 128;
    const int wm = wid & 1;          // 2 M-warps of 64 rows
    const int wn = wid >> 1;         // 4 N-warps of 32 cols

    // global load assignment: row rr, 32 cols starting at kh
    const int rr = tid >> 1;
    const int kh = (tid & 1) * 32;
    const float* Xr = X + (size_t)(m0 + rr) * DIM + kh;
    const float* Wr = W + (size_t)(n0 + rr) * DIM + kh;
    const uint32_t rx_w = ((uint32_t)rr & 7u) << 4;   // writer swizzle
    const uint32_t wbase = (uint32_t)rr * 128u;

    // ldmatrix lane geometry
    // A: sub = lane>>3: row += (sub&1)*8, cb += (sub>>1)*16
    const int a_rin = (lane & 7) + ((lane >> 3) & 1) * 8;
    const int a_cbs = (lane >> 4) * 16;
    // B: row += (sub>>1)*8, cb += (sub&1)*16
    const int b_rin = (lane & 7) + (lane >> 4) * 8;
    const int b_cbs = ((lane >> 3) & 1) * 16;

    uint32_t aoff[4], arx[4];
#pragma unroll
    for (int t = 0; t < 4; t++) {
        const uint32_t r = (uint32_t)(wm * 64 + t * 16 + a_rin);
        aoff[t] = r * 128u;
        arx[t] = (r & 7u) << 4;
    }
    uint32_t boff[2], brx[2];
#pragma unroll
    for (int u = 0; u < 2; u++) {
        const uint32_t r = (uint32_t)(wn * 32 + u * 16 + b_rin);
        boff[u] = r * 128u;
        brx[u] = (r & 7u) << 4;
    }

    float acc[4][4][4];
#pragma unroll
    for (int i = 0; i < 4; i++)
#pragma unroll
        for (int j = 0; j < 4; j++)
#pragma unroll
            for (int c = 0; c < 4; c++) acc[i][j][c] = 0.f;

    for (int it = 0; it < 16; it++) {
        float4 av[8], bv[8];
#pragma unroll
        for (int i = 0; i < 8; i++) {
            av[i] = *(const float4*)(Xr + it * 64 + i * 4);
            bv[i] = *(const float4*)(Wr + it * 64 + i * 4);
        }
        __syncthreads();   // previous iter consumed
#pragma unroll
        for (int i = 0; i < 8; i++) {
            const uint32_t cb = (uint32_t)(kh * 2 + i * 8);
            const uint32_t so = wbase + (cb ^ rx_w);
            uint2 hi, lo;
            split4(av[i], hi, lo);
            *(uint2*)(smc + SM_AH + so) = hi;
            *(uint2*)(smc + SM_AL + so) = lo;
            split4(bv[i], hi, lo);
            *(uint2*)(smc + SM_BH + so) = hi;
            *(uint2*)(smc + SM_BL + so) = lo;
        }
        __syncthreads();

#pragma unroll
        for (int kk = 0; kk < 4; kk++) {
            const uint32_t acb = (uint32_t)(kk * 32 + a_cbs);
            const uint32_t bcb = (uint32_t)(kk * 32 + b_cbs);
            uint32_t bh[2][4], bl[2][4];
#pragma unroll
            for (int u = 0; u < 2; u++) {
                const uint32_t ad = boff[u] + (bcb ^ brx[u]);
                LDSM4(bh[u][0], bh[u][1], bh[u][2], bh[u][3], sb + SM_BH + ad);
                LDSM4(bl[u][0], bl[u][1], bl[u][2], bl[u][3], sb + SM_BL + ad);
            }
#pragma unroll
            for (int t = 0; t < 4; t++) {
                const uint32_t ad = aoff[t] + (acb ^ arx[t]);
                uint32_t ah[4], al[4];
                LDSM4(ah[0], ah[1], ah[2], ah[3], sb + SM_AH + ad);
                LDSM4(al[0], al[1], al[2], al[3], sb + SM_AL + ad);
#pragma unroll
                for (int nt = 0; nt < 4; nt++) {
                    const int u = nt >> 1, h2 = (nt & 1) * 2;
                    MMA16816(acc[t][nt], ah[0], ah[1], ah[2], ah[3],
                             bh[u][h2], bh[u][h2 + 1]);
                    MMA16816(acc[t][nt], ah[0], ah[1], ah[2], ah[3],
                             bl[u][h2], bl[u][h2 + 1]);
                    MMA16816(acc[t][nt], al[0], al[1], al[2], al[3],
                             bh[u][h2], bh[u][h2 + 1]);
                }
            }
        }
    }

    // Epilogue: acc[mt][nt]: rows = m0+wm*64+mt*16+(lane>>2)+{0,8},
    //           cols = n0+wn*32+nt*8+(lane&3)*2+{0,1}
#pragma unroll
    for (int mt = 0; mt < 4; mt++) {
        const int m1 = m0 + wm * 64 + mt * 16 + (lane >> 2);
        const int m2 = m1 + 8;
#pragma unroll
        for (int nt = 0; nt < 4; nt++) {
            const int n = n0 + wn * 32 + nt * 8 + (lane & 3) * 2;
            const float b0v = bias[n], b1v = bias[n + 1];
            const float v00 = acc[mt][nt][0] + b0v;
            const float v01 = acc[mt][nt][1] + b1v;
            const float v10 = acc[mt][nt][2] + b0v;
            const float v11 = acc[mt][nt][3] + b1v;
            if (mode == 0) {
                *(float2*)(out + (size_t)m1 * DIM + n) = make_float2(v00, v01);
                *(float2*)(out + (size_t)m2 * DIM + n) = make_float2(v10, v11);
            } else if (mode == 1) {
                const int h = n >> 6, hd = n & 63;
                const int b1i = m1 >> 11, s1 = m1 & 2047;
                const int b2i = m2 >> 11, s2 = m2 & 2047;
                *(float2*)(out + (((size_t)b1i * NHEAD + h) * SEQ + s1) * HDIM + hd) =
                    make_float2(v00, v01);
                *(float2*)(out + (((size_t)b2i * NHEAD + h) * SEQ + s2) * HDIM + hd) =
                    make_float2(v10, v11);
            } else {  // transposed [B,H,HD,S]
                const int h = n >> 6, hd = n & 63;
                const int b1i = m1 >> 11, s1 = m1 & 2047;
                const int b2i = m2 >> 11, s2 = m2 & 2047;
                float* d0 = out + (((size_t)b1i * NHEAD + h) * HDIM + hd) * SEQ;
                float* d1 = out + (((size_t)b2i * NHEAD + h) * HDIM + hd) * SEQ;
                d0[s1] = v00;
                d0[SEQ + s1] = v01;
                d1[s2] = v10;
                d1[SEQ + s2] = v11;
            }
        }
    }
}

// ---------------------------------------------------------------------------
// Register-tiled flash attention. Block = (b,h,64-row Q tile), 128 threads.
// Thread (ty 0..7, tx 0..15) owns 8 rows x 4 keys of S and 8 rows x 4 dims of O.
// ---------------------------------------------------------------------------
#define ATTN_SMEM 65536

__global__ __launch_bounds__(128)
void attn_tile(const float* __restrict__ qT, const float* __restrict__ kT,
               const float* __restrict__ V, float* __restrict__ O)
{
    extern __shared__ __align__(16) float smf[];
    float* Qt = smf;             // [64][64]  (d, r)
    float* Kt = Qt + 4096;       // [64][64]  (d, c)
    float* Vs = Kt + 4096;       // [64][64]  (k, d)
    float* Ps = Vs + 4096;       // [64][64]  (k, r^swz)

    const int qt = blockIdx.x, h = blockIdx.y, b = blockIdx.z;
    const int tid = threadIdx.x;
    const int ty = tid >> 4, tx = tid & 15;
    const size_t bh = (size_t)(b * NHEAD + h);
    const float* qbase = qT + bh * HDIM * SEQ + (size_t)qt * 64;
    const float* kbase = kT + bh * HDIM * SEQ;
    const float* vbase = V + bh * SEQ * HDIM;

    for (int i = tid; i < 64 * 16; i += 128) {
        const int d = i >> 4, r4 = (i & 15) * 4;
        float4 v = *(const float4*)(qbase + (size_t)d * SEQ + r4);
        v.x *= 0.125f; v.y *= 0.125f; v.z *= 0.125f; v.w *= 0.125f;
        *(float4*)(Qt + d * 64 + r4) = v;
    }

    float o[8][4];
    float mr[8], lr[8];
#pragma unroll
    for (int i = 0; i < 8; i++) {
        mr[i] = -1e30f; lr[i] = 0.f;
#pragma unroll
        for (int j = 0; j < 4; j++) o[i][j] = 0.f;
    }

    for (int kc = 0; kc < SEQ; kc += 64) {
        __syncthreads();
        for (int i = tid; i < 64 * 16; i += 128) {
            const int r = i >> 4, c4 = (i & 15) * 4;
            *(float4*)(Kt + r * 64 + c4) = *(const float4*)(kbase + (size_t)r * SEQ + kc + c4);
            *(float4*)(Vs + r * 64 + c4) = *(const float4*)(vbase + (size_t)(kc + r) * HDIM + c4);
        }
        __syncthreads();

        float sc[8][4];
#pragma unroll
        for (int i = 0; i < 8; i++)
#pragma unroll
            for (int j = 0; j < 4; j++) sc[i][j] = 0.f;

        const float* qp = Qt + ty * 8;
        const float* kp = Kt + tx * 4;
#pragma unroll 4
        for (int d = 0; d < 64; d++) {
            float4 a0 = *(const float4*)(qp + d * 64);
            float4 a1 = *(const float4*)(qp + d * 64 + 4);
            float4 b4 = *(const float4*)(kp + d * 64);
            const float aa[8] = {a0.x, a0.y, a0.z, a0.w, a1.x, a1.y, a1.z, a1.w};
            const float bb4[4] = {b4.x, b4.y, b4.z, b4.w};
#pragma unroll
            for (int i = 0; i < 8; i++)
#pragma unroll
                for (int j = 0; j < 4; j++)
                    sc[i][j] = fmaf(aa[i], bb4[j], sc[i][j]);
        }

#pragma unroll
        for (int i = 0; i < 8; i++) {
            float mc = fmaxf(fmaxf(sc[i][0], sc[i][1]), fmaxf(sc[i][2], sc[i][3]));
            mc = fmaxf(mc, __shfl_xor_sync(0xffffffffu, mc, 1));
            mc = fmaxf(mc, __shfl_xor_sync(0xffffffffu, mc, 2));
            mc = fmaxf(mc, __shfl_xor_sync(0xffffffffu, mc, 4));
            mc = fmaxf(mc, __shfl_xor_sync(0xffffffffu, mc, 8));
            const float mn = fmaxf(mr[i], mc);
            const float al = __expf(mr[i] - mn);
            mr[i] = mn;
            float ps = 0.f;
#pragma unroll
            for (int j = 0; j < 4; j++) {
                sc[i][j] = __expf(sc[i][j] - mn);
                ps += sc[i][j];
            }
            ps += __shfl_xor_sync(0xffffffffu, ps, 1);
            ps += __shfl_xor_sync(0xffffffffu, ps, 2);
            ps += __shfl_xor_sync(0xffffffffu, ps, 4);
            ps += __shfl_xor_sync(0xffffffffu, ps, 8);
            lr[i] = lr[i] * al + ps;
#pragma unroll
            for (int j = 0; j < 4; j++) o[i][j] *= al;
            const int xr = (ty * 8 + i) ^ (tx * 4);
#pragma unroll
            for (int j = 0; j < 4; j++)
                Ps[(tx * 4 + j) * 64 + xr] = sc[i][j];
        }
        __syncthreads();

#pragma unroll 4
        for (int k = 0; k < 64; k++) {
            const int ks = ((k >> 2) & 15) * 4;
            float4 p0 = *(const float4*)(Ps + k * 64 + ((ty * 8) ^ ks));
            float4 p1 = *(const float4*)(Ps + k * 64 + ((ty * 8 + 4) ^ ks));
            float4 vv = *(const float4*)(Vs + k * 64 + tx * 4);
            const float pp[8] = {p0.x, p0.y, p0.z, p0.w, p1.x, p1.y, p1.z, p1.w};
            const float vj[4] = {vv.x, vv.y, vv.z, vv.w};
#pragma unroll
            for (int i = 0; i < 8; i++)
#pragma unroll
                for (int j = 0; j < 4; j++)
                    o[i][j] = fmaf(pp[i], vj[j], o[i][j]);
        }
    }

    float* ob = O + ((size_t)(b * SEQ) + qt * 64) * DIM + h * HDIM;
#pragma unroll
    for (int i = 0; i < 8; i++) {
        const float inv = 1.f / lr[i];
        float4 w4 = make_float4(o[i][0] * inv, o[i][1] * inv, o[i][2] * inv, o[i][3] * inv);
        *(float4*)(ob + (size_t)(ty * 8 + i) * DIM + tx * 4) = w4;
    }
}

// ---------------------------------------------------------------------------
extern "C" void kernel_launch(void* const* d_in, const int* in_sizes, int n_in,
                              void* d_out, int out_size)
{
    const float* query = (const float*)d_in[0];
    const float* key   = (const float*)d_in[1];
    const float* value = (const float*)d_in[2];
    const float* Wq = (const float*)d_in[3];
    const float* bq = (const float*)d_in[4];
    const float* Wk = (const float*)d_in[5];
    const float* bk = (const float*)d_in[6];
    const float* Wv = (const float*)d_in[7];
    const float* bv = (const float*)d_in[8];
    const float* Wo = (const float*)d_in[9];
    const float* bo = (const float*)d_in[10];
    float* out = (float*)d_out;

    float *qT, *kT, *vv, *at;
    cudaGetSymbolAddress((void**)&qT, g_qT);
    cudaGetSymbolAddress((void**)&kT, g_kT);
    cudaGetSymbolAddress((void**)&vv, g_v);
    cudaGetSymbolAddress((void**)&at, g_at);

    cudaFuncSetAttribute(proj_mma, cudaFuncAttributeMaxDynamicSharedMemorySize, PROJ_SMEM);
    cudaFuncSetAttribute(attn_tile, cudaFuncAttributeMaxDynamicSharedMemorySize, ATTN_SMEM);

    dim3 pg(DIM / 128, MROWS / 128);   // (8, 64)
    proj_mma<<<pg, 256, PROJ_SMEM>>>(query, Wq, bq, qT, 2);
    proj_mma<<<pg, 256, PROJ_SMEM>>>(key,   Wk, bk, kT, 2);
    proj_mma<<<pg, 256, PROJ_SMEM>>>(value, Wv, bv, vv, 1);

    dim3 ag(SEQ / 64, NHEAD, BBATCH);  // (32, 16, 4)
    attn_tile<<<ag, 128, ATTN_SMEM>>>(qT, kT, vv, at);

    proj_mma<<<pg, 256, PROJ_SMEM>>>(at, Wo, bo, out, 0);
}

// round 4
// speedup vs baseline: 3.3079x; 1.5487x over previous
#include <cuda_runtime.h>
#include <cuda_bf16.h>
#include <stdint.h>

#define BBATCH 4
#define SEQ 2048
#define DIM 1024
#define NHEAD 16
#define HDIM 64
#define MROWS (BBATCH * SEQ)   // 8192

// Scratch (device globals; no allocation)
__device__ __nv_bfloat16 g_qh[BBATCH * NHEAD * SEQ * HDIM];  // [B,H,S,HD] hi
__device__ __nv_bfloat16 g_ql[BBATCH * NHEAD * SEQ * HDIM];  // lo
__device__ __nv_bfloat16 g_kh[BBATCH * NHEAD * SEQ * HDIM];  // [B,H,S,HD]
__device__ __nv_bfloat16 g_kl[BBATCH * NHEAD * SEQ * HDIM];
__device__ __nv_bfloat16 g_vh[BBATCH * NHEAD * HDIM * SEQ];  // [B,H,HD,S] (transposed)
__device__ __nv_bfloat16 g_vl[BBATCH * NHEAD * HDIM * SEQ];
__device__ float g_at[BBATCH * SEQ * DIM];                   // [B,S,D]

// ---------------------------------------------------------------------------
__device__ __forceinline__ uint32_t s2u(const void* p) {
    uint32_t a;
    asm("{ .reg .u64 t; cvta.to.shared.u64 t, %1; cvt.u32.u64 %0, t; }" : "=r"(a) : "l"(p));
    return a;
}

#define LDSM4(r0, r1, r2, r3, a) \
    asm volatile("ldmatrix.sync.aligned.m8n8.x4.shared.b16 {%0,%1,%2,%3}, [%4];" \
                 : "=r"(r0), "=r"(r1), "=r"(r2), "=r"(r3) : "r"(a))

#define MMA16816(d, a0, a1, a2, a3, b0, b1) \
    asm volatile("mma.sync.aligned.m16n8k16.row.col.f32.bf16.bf16.f32 " \
                 "{%0,%1,%2,%3},{%4,%5,%6,%7},{%8,%9},{%0,%1,%2,%3};" \
                 : "+f"((d)[0]), "+f"((d)[1]), "+f"((d)[2]), "+f"((d)[3]) \
                 : "r"(a0), "r"(a1), "r"(a2), "r"(a3), "r"(b0), "r"(b1))

#define CP16(d, s) \
    asm volatile("cp.async.cg.shared.global [%0], [%1], 16;" :: "r"(d), "l"(s))
#define CP_COMMIT() asm volatile("cp.async.commit_group;" ::: "memory")
#define CP_WAIT(n)  asm volatile("cp.async.wait_group %0;" :: "n"(n) : "memory")

// split fp32 pair -> packed bf16x2 hi and lo
__device__ __forceinline__ void split2(float a, float b, uint32_t& h, uint32_t& l) {
    __nv_bfloat16 ha = __float2bfloat16_rn(a);
    __nv_bfloat16 hb = __float2bfloat16_rn(b);
    float la = a - __bfloat162float(ha);
    float lb = b - __bfloat162float(hb);
    __nv_bfloat162 H = __halves2bfloat162(ha, hb);
    __nv_bfloat162 L = __floats2bfloat162_rn(la, lb);
    h = *reinterpret_cast<uint32_t*>(&H);
    l = *reinterpret_cast<uint32_t*>(&L);
}
__device__ __forceinline__ void split4(float4 v, uint2& hi, uint2& lo) {
    split2(v.x, v.y, hi.x, lo.x);
    split2(v.z, v.w, hi.y, lo.y);
}

// ---------------------------------------------------------------------------
// mma.sync projection GEMM: Y[8192,1024] = X @ W^T + bias  (then * scale)
// mode 0: fp32 [M,N] -> outA
// mode 1: bf16 split -> outA/outB as [B,H,S,HD]
// mode 2: bf16 split transposed -> outA/outB as [B,H,HD,S]
// ---------------------------------------------------------------------------
#define SM_AH 0
#define SM_AL 16384
#define SM_BH 32768
#define SM_BL 49152
#define PROJ_SMEM 65536

__global__ __launch_bounds__(256, 2)
void proj_mma(const float* __restrict__ X, const float* __restrict__ W,
              const float* __restrict__ bias, void* outA, void* outB,
              int mode, float scale)
{
    extern __shared__ __align__(128) char smc[];
    const uint32_t sb = s2u(smc);
    const int tid = threadIdx.x;
    const int wid = tid >> 5;
    const int lane = tid & 31;

    const int m0 = blockIdx.y * 128;
    const int n0 = blockIdx.x * 128;
    const int wm = wid & 1;
    const int wn = wid >> 1;

    const int rr = tid >> 1;
    const int kh = (tid & 1) * 32;
    const float* Xr = X + (size_t)(m0 + rr) * DIM + kh;
    const float* Wr = W + (size_t)(n0 + rr) * DIM + kh;
    const uint32_t rx_w = ((uint32_t)rr & 7u) << 4;
    const uint32_t wbase = (uint32_t)rr * 128u;

    const int a_rin = (lane & 7) + ((lane >> 3) & 1) * 8;
    const int a_cbs = (lane >> 4) * 16;
    const int b_rin = (lane & 7) + (lane >> 4) * 8;
    const int b_cbs = ((lane >> 3) & 1) * 16;

    uint32_t aoff[4], arx[4];
#pragma unroll
    for (int t = 0; t < 4; t++) {
        const uint32_t r = (uint32_t)(wm * 64 + t * 16 + a_rin);
        aoff[t] = r * 128u;
        arx[t] = (r & 7u) << 4;
    }
    uint32_t boff[2], brx[2];
#pragma unroll
    for (int u = 0; u < 2; u++) {
        const uint32_t r = (uint32_t)(wn * 32 + u * 16 + b_rin);
        boff[u] = r * 128u;
        brx[u] = (r & 7u) << 4;
    }

    float acc[4][4][4];
#pragma unroll
    for (int i = 0; i < 4; i++)
#pragma unroll
        for (int j = 0; j < 4; j++)
#pragma unroll
            for (int c = 0; c < 4; c++) acc[i][j][c] = 0.f;

    for (int it = 0; it < 16; it++) {
        float4 av[8], bv[8];
#pragma unroll
        for (int i = 0; i < 8; i++) {
            av[i] = *(const float4*)(Xr + it * 64 + i * 4);
            bv[i] = *(const float4*)(Wr + it * 64 + i * 4);
        }
        __syncthreads();
#pragma unroll
        for (int i = 0; i < 8; i++) {
            const uint32_t cb = (uint32_t)(kh * 2 + i * 8);
            const uint32_t so = wbase + (cb ^ rx_w);
            uint2 hi, lo;
            split4(av[i], hi, lo);
            *(uint2*)(smc + SM_AH + so) = hi;
            *(uint2*)(smc + SM_AL + so) = lo;
            split4(bv[i], hi, lo);
            *(uint2*)(smc + SM_BH + so) = hi;
            *(uint2*)(smc + SM_BL + so) = lo;
        }
        __syncthreads();

#pragma unroll
        for (int kk = 0; kk < 4; kk++) {
            const uint32_t acb = (uint32_t)(kk * 32 + a_cbs);
            const uint32_t bcb = (uint32_t)(kk * 32 + b_cbs);
            uint32_t bh[2][4], bl[2][4];
#pragma unroll
            for (int u = 0; u < 2; u++) {
                const uint32_t ad = boff[u] + (bcb ^ brx[u]);
                LDSM4(bh[u][0], bh[u][1], bh[u][2], bh[u][3], sb + SM_BH + ad);
                LDSM4(bl[u][0], bl[u][1], bl[u][2], bl[u][3], sb + SM_BL + ad);
            }
#pragma unroll
            for (int t = 0; t < 4; t++) {
                const uint32_t ad = aoff[t] + (acb ^ arx[t]);
                uint32_t ah[4], al[4];
                LDSM4(ah[0], ah[1], ah[2], ah[3], sb + SM_AH + ad);
                LDSM4(al[0], al[1], al[2], al[3], sb + SM_AL + ad);
#pragma unroll
                for (int nt = 0; nt < 4; nt++) {
                    const int u = nt >> 1, h2 = (nt & 1) * 2;
                    MMA16816(acc[t][nt], ah[0], ah[1], ah[2], ah[3],
                             bh[u][h2], bh[u][h2 + 1]);
                    MMA16816(acc[t][nt], ah[0], ah[1], ah[2], ah[3],
                             bl[u][h2], bl[u][h2 + 1]);
                    MMA16816(acc[t][nt], al[0], al[1], al[2], al[3],
                             bh[u][h2], bh[u][h2 + 1]);
                }
            }
        }
    }

#pragma unroll
    for (int mt = 0; mt < 4; mt++) {
        const int m1 = m0 + wm * 64 + mt * 16 + (lane >> 2);
        const int m2 = m1 + 8;
#pragma unroll
        for (int nt = 0; nt < 4; nt++) {
            const int n = n0 + wn * 32 + nt * 8 + (lane & 3) * 2;
            const float b0v = bias[n], b1v = bias[n + 1];
            const float v00 = (acc[mt][nt][0] + b0v) * scale;
            const float v01 = (acc[mt][nt][1] + b1v) * scale;
            const float v10 = (acc[mt][nt][2] + b0v) * scale;
            const float v11 = (acc[mt][nt][3] + b1v) * scale;
            if (mode == 0) {
                float* out = (float*)outA;
                *(float2*)(out + (size_t)m1 * DIM + n) = make_float2(v00, v01);
                *(float2*)(out + (size_t)m2 * DIM + n) = make_float2(v10, v11);
            } else {
                const int h = n >> 6, hd = n & 63;
                const int b1i = m1 >> 11, s1 = m1 & 2047;
                const int b2i = m2 >> 11, s2 = m2 & 2047;
                __nv_bfloat16* oh = (__nv_bfloat16*)outA;
                __nv_bfloat16* ol = (__nv_bfloat16*)outB;
                uint32_t h0, l0, h1, l1;
                split2(v00, v01, h0, l0);
                split2(v10, v11, h1, l1);
                if (mode == 1) {
                    const size_t i1 = (((size_t)b1i * NHEAD + h) * SEQ + s1) * HDIM + hd;
                    const size_t i2 = (((size_t)b2i * NHEAD + h) * SEQ + s2) * HDIM + hd;
                    *(uint32_t*)(oh + i1) = h0;
                    *(uint32_t*)(ol + i1) = l0;
                    *(uint32_t*)(oh + i2) = h1;
                    *(uint32_t*)(ol + i2) = l1;
                } else {  // transposed [B,H,HD,S]
                    const size_t t1 = (((size_t)b1i * NHEAD + h) * HDIM + hd) * SEQ + s1;
                    const size_t t2 = (((size_t)b2i * NHEAD + h) * HDIM + hd) * SEQ + s2;
                    oh[t1] = __float2bfloat16_rn(v00);
                    ol[t1] = __float2bfloat16_rn(v00 - __bfloat162float(__float2bfloat16_rn(v00)));
                    oh[t1 + SEQ] = __float2bfloat16_rn(v01);
                    ol[t1 + SEQ] = __float2bfloat16_rn(v01 - __bfloat162float(__float2bfloat16_rn(v01)));
                    oh[t2] = __float2bfloat16_rn(v10);
                    ol[t2] = __float2bfloat16_rn(v10 - __bfloat162float(__float2bfloat16_rn(v10)));
                    oh[t2 + SEQ] = __float2bfloat16_rn(v11);
                    ol[t2 + SEQ] = __float2bfloat16_rn(v11 - __bfloat162float(__float2bfloat16_rn(v11)));
                }
            }
        }
    }
}

// ---------------------------------------------------------------------------
// Tensor-core flash attention.
// CTA = (qtile of 128 rows, h, b), 256 threads = 8 warps, warp owns m16.
// K/V chunks of 64 keys, cp.async double-buffered. Split-bf16 3-MMA everywhere.
// Smem: QH 16K | QL 16K | buf0 {KH,KL,VH,VL}4x8K | buf1 4x8K  = 96KB
// ---------------------------------------------------------------------------
#define AQ_H 0
#define AQ_L 16384
#define ABUF0 32768
#define ABUF_SZ 32768
#define ATTN_SMEM 98304

__global__ __launch_bounds__(256, 1)
void attn_mma(const __nv_bfloat16* __restrict__ qh_g, const __nv_bfloat16* __restrict__ ql_g,
              const __nv_bfloat16* __restrict__ kh_g, const __nv_bfloat16* __restrict__ kl_g,
              const __nv_bfloat16* __restrict__ vh_g, const __nv_bfloat16* __restrict__ vl_g,
              float* __restrict__ O)
{
    extern __shared__ __align__(128) char smc[];
    const uint32_t sb = s2u(smc);
    const int tid = threadIdx.x;
    const int wid = tid >> 5;
    const int lane = tid & 31;

    const int qt = blockIdx.x, h = blockIdx.y, b = blockIdx.z;
    const size_t bh = (size_t)(b * NHEAD + h);
    const int q0 = qt * 128;

    // ---- cp.async source/dest geometry ----
    // Q: thread t: array a=t>>7 (0=hi,1=lo), row=t&127 (8 chunks of 16B)
    {
        const int a = tid >> 7, r = tid & 127;
        const char* src = (const char*)((a == 0 ? qh_g : ql_g) + (bh * SEQ + q0 + r) * HDIM);
        const uint32_t dst = sb + (a == 0 ? AQ_H : AQ_L) + (uint32_t)r * 128u;
        const uint32_t swz = ((uint32_t)r & 7u) << 4;
#pragma unroll
        for (int i = 0; i < 8; i++)
            CP16(dst + ((uint32_t)(i * 16) ^ swz), src + i * 16);
        CP_COMMIT();
    }

    // chunk loader: array a = tid>>6 (KH,KL,VH,VL), row = tid&63
    const int ca = tid >> 6, cr = tid & 63;
    const char* csrc0;
    {
        const __nv_bfloat16* gp;
        size_t off;
        if (ca == 0) { gp = kh_g; off = (bh * SEQ + cr) * HDIM; }
        else if (ca == 1) { gp = kl_g; off = (bh * SEQ + cr) * HDIM; }
        else if (ca == 2) { gp = vh_g; off = (bh * HDIM + cr) * SEQ; }
        else { gp = vl_g; off = (bh * HDIM + cr) * SEQ; }
        csrc0 = (const char*)(gp + off);
    }
    const size_t cstep = (ca < 2) ? (size_t)64 * HDIM * 2 : (size_t)64 * 2;  // bytes per 64-key advance
    const uint32_t cdst_base = sb + ABUF0 + (uint32_t)ca * 8192u + (uint32_t)cr * 128u;
    const uint32_t cswz = ((uint32_t)cr & 7u) << 4;

    // prefetch chunk 0
    {
        const char* src = csrc0;
#pragma unroll
        for (int i = 0; i < 8; i++)
            CP16(cdst_base + ((uint32_t)(i * 16) ^ cswz), src + i * 16);
        CP_COMMIT();
    }

    // wait for Q (allow chunk0 outstanding)
    CP_WAIT(1);
    __syncthreads();

    // ---- load Q fragments to registers ----
    const int arow = wid * 16 + (lane & 7) + ((lane >> 3) & 1) * 8;
    const uint32_t aswz = ((uint32_t)lane & 7u) << 4;
    uint32_t qfh[4][4], qfl[4][4];
#pragma unroll
    for (int kt = 0; kt < 4; kt++) {
        const uint32_t cb = (uint32_t)(kt * 32 + (lane >> 4) * 16);
        const uint32_t ad = (uint32_t)arow * 128u + (cb ^ aswz);
        LDSM4(qfh[kt][0], qfh[kt][1], qfh[kt][2], qfh[kt][3], sb + AQ_H + ad);
        LDSM4(qfl[kt][0], qfl[kt][1], qfl[kt][2], qfl[kt][3], sb + AQ_L + ad);
    }

    // B-fragment lane geometry (shared by K and V)
    const int brow = (lane & 7) + (lane >> 4) * 8;   // within 16-row group
    const uint32_t bswz = ((uint32_t)lane & 7u) << 4;
    const uint32_t bcbs = (uint32_t)(((lane >> 3) & 1) * 16);

    float oacc[8][4];
#pragma unroll
    for (int t = 0; t < 8; t++)
#pragma unroll
        for (int j = 0; j < 4; j++) oacc[t][j] = 0.f;
    float m1 = -1e30f, m2 = -1e30f, l1 = 0.f, l2 = 0.f;

    const int NCHUNK = SEQ / 64;  // 32
    for (int c = 0; c < NCHUNK; c++) {
        // prefetch next chunk
        if (c + 1 < NCHUNK) {
            const char* src = csrc0 + (size_t)(c + 1) * cstep;
            const uint32_t dst = cdst_base + (uint32_t)(((c + 1) & 1) * ABUF_SZ);
#pragma unroll
            for (int i = 0; i < 8; i++)
                CP16(dst + ((uint32_t)(i * 16) ^ cswz), src + i * 16);
            CP_COMMIT();
            CP_WAIT(1);
        } else {
            CP_WAIT(0);
        }
        __syncthreads();

        const uint32_t kb_h = sb + ABUF0 + (uint32_t)((c & 1) * ABUF_SZ);
        const uint32_t kb_l = kb_h + 8192u;
        const uint32_t vb_h = kb_h + 16384u;
        const uint32_t vb_l = kb_h + 24576u;

        // ---- S = Q K^T ----
        float sc[8][4];
#pragma unroll
        for (int t = 0; t < 8; t++)
#pragma unroll
            for (int j = 0; j < 4; j++) sc[t][j] = 0.f;

#pragma unroll
        for (int kt = 0; kt < 4; kt++) {
            uint32_t kfh[4][4], kfl[4][4];
#pragma unroll
            for (int u = 0; u < 4; u++) {
                const uint32_t ad = (uint32_t)(16 * u + brow) * 128u +
                                    (((uint32_t)(kt * 32) + bcbs) ^ bswz);
                LDSM4(kfh[u][0], kfh[u][1], kfh[u][2], kfh[u][3], kb_h + ad);
                LDSM4(kfl[u][0], kfl[u][1], kfl[u][2], kfl[u][3], kb_l + ad);
            }
#pragma unroll
            for (int nt = 0; nt < 8; nt++) {
                const int u = nt >> 1, h2 = (nt & 1) * 2;
                MMA16816(sc[nt], qfh[kt][0], qfh[kt][1], qfh[kt][2], qfh[kt][3],
                         kfh[u][h2], kfh[u][h2 + 1]);
                MMA16816(sc[nt], qfh[kt][0], qfh[kt][1], qfh[kt][2], qfh[kt][3],
                         kfl[u][h2], kfl[u][h2 + 1]);
                MMA16816(sc[nt], qfl[kt][0], qfl[kt][1], qfl[kt][2], qfl[kt][3],
                         kfh[u][h2], kfh[u][h2 + 1]);
            }
        }

        // ---- online softmax (rows r1=lane>>2, r2=r1+8) ----
        float mx1 = sc[0][0], mx2 = sc[0][2];
#pragma unroll
        for (int t = 0; t < 8; t++) {
            mx1 = fmaxf(mx1, fmaxf(sc[t][0], sc[t][1]));
            mx2 = fmaxf(mx2, fmaxf(sc[t][2], sc[t][3]));
        }
        mx1 = fmaxf(mx1, __shfl_xor_sync(0xffffffffu, mx1, 1));
        mx1 = fmaxf(mx1, __shfl_xor_sync(0xffffffffu, mx1, 2));
        mx2 = fmaxf(mx2, __shfl_xor_sync(0xffffffffu, mx2, 1));
        mx2 = fmaxf(mx2, __shfl_xor_sync(0xffffffffu, mx2, 2));
        const float mn1 = fmaxf(m1, mx1), mn2 = fmaxf(m2, mx2);
        const float al1 = __expf(m1 - mn1), al2 = __expf(m2 - mn2);
        m1 = mn1; m2 = mn2;
        l1 *= al1; l2 *= al2;
#pragma unroll
        for (int t = 0; t < 8; t++) {
            sc[t][0] = __expf(sc[t][0] - m1);
            sc[t][1] = __expf(sc[t][1] - m1);
            sc[t][2] = __expf(sc[t][2] - m2);
            sc[t][3] = __expf(sc[t][3] - m2);
            l1 += sc[t][0] + sc[t][1];
            l2 += sc[t][2] + sc[t][3];
            oacc[t][0] *= al1; oacc[t][1] *= al1;
            oacc[t][2] *= al2; oacc[t][3] *= al2;
        }

        // ---- O += P V ----
#pragma unroll
        for (int kt = 0; kt < 4; kt++) {
            uint32_t ph[4], pl[4];
            split2(sc[2 * kt][0], sc[2 * kt][1], ph[0], pl[0]);
            split2(sc[2 * kt][2], sc[2 * kt][3], ph[1], pl[1]);
            split2(sc[2 * kt + 1][0], sc[2 * kt + 1][1], ph[2], pl[2]);
            split2(sc[2 * kt + 1][2], sc[2 * kt + 1][3], ph[3], pl[3]);

            uint32_t vfh[4][4], vfl[4][4];
#pragma unroll
            for (int u = 0; u < 4; u++) {
                const uint32_t ad = (uint32_t)(16 * u + brow) * 128u +
                                    (((uint32_t)(kt * 32) + bcbs) ^ bswz);
                LDSM4(vfh[u][0], vfh[u][1], vfh[u][2], vfh[u][3], vb_h + ad);
                LDSM4(vfl[u][0], vfl[u][1], vfl[u][2], vfl[u][3], vb_l + ad);
            }
#pragma unroll
            for (int nt = 0; nt < 8; nt++) {
                const int u = nt >> 1, h2 = (nt & 1) * 2;
                MMA16816(oacc[nt], ph[0], ph[1], ph[2], ph[3],
                         vfh[u][h2], vfh[u][h2 + 1]);
                MMA16816(oacc[nt], ph[0], ph[1], ph[2], ph[3],
                         vfl[u][h2], vfl[u][h2 + 1]);
                MMA16816(oacc[nt], pl[0], pl[1], pl[2], pl[3],
                         vfh[u][h2], vfh[u][h2 + 1]);
            }
        }
        __syncthreads();
    }

    // final l reduction across the quad
    l1 += __shfl_xor_sync(0xffffffffu, l1, 1);
    l1 += __shfl_xor_sync(0xffffffffu, l1, 2);
    l2 += __shfl_xor_sync(0xffffffffu, l2, 1);
    l2 += __shfl_xor_sync(0xffffffffu, l2, 2);
    const float inv1 = 1.f / l1, inv2 = 1.f / l2;

    const int r1 = q0 + wid * 16 + (lane >> 2);
    float* o1 = O + ((size_t)b * SEQ + r1) * DIM + h * HDIM + (lane & 3) * 2;
    float* o2 = o1 + (size_t)8 * DIM;
#pragma unroll
    for (int t = 0; t < 8; t++) {
        *(float2*)(o1 + t * 8) = make_float2(oacc[t][0] * inv1, oacc[t][1] * inv1);
        *(float2*)(o2 + t * 8) = make_float2(oacc[t][2] * inv2, oacc[t][3] * inv2);
    }
}

// ---------------------------------------------------------------------------
extern "C" void kernel_launch(void* const* d_in, const int* in_sizes, int n_in,
                              void* d_out, int out_size)
{
    const float* query = (const float*)d_in[0];
    const float* key   = (const float*)d_in[1];
    const float* value = (const float*)d_in[2];
    const float* Wq = (const float*)d_in[3];
    const float* bq = (const float*)d_in[4];
    const float* Wk = (const float*)d_in[5];
    const float* bk = (const float*)d_in[6];
    const float* Wv = (const float*)d_in[7];
    const float* bv = (const float*)d_in[8];
    const float* Wo = (const float*)d_in[9];
    const float* bo = (const float*)d_in[10];
    float* out = (float*)d_out;

    __nv_bfloat16 *qh, *ql, *kh, *kl, *vh, *vl;
    float* at;
    cudaGetSymbolAddress((void**)&qh, g_qh);
    cudaGetSymbolAddress((void**)&ql, g_ql);
    cudaGetSymbolAddress((void**)&kh, g_kh);
    cudaGetSymbolAddress((void**)&kl, g_kl);
    cudaGetSymbolAddress((void**)&vh, g_vh);
    cudaGetSymbolAddress((void**)&vl, g_vl);
    cudaGetSymbolAddress((void**)&at, g_at);

    cudaFuncSetAttribute(proj_mma, cudaFuncAttributeMaxDynamicSharedMemorySize, PROJ_SMEM);
    cudaFuncSetAttribute(attn_mma, cudaFuncAttributeMaxDynamicSharedMemorySize, ATTN_SMEM);

    dim3 pg(DIM / 128, MROWS / 128);   // (8, 64)
    proj_mma<<<pg, 256, PROJ_SMEM>>>(query, Wq, bq, qh, ql, 1, 0.125f);
    proj_mma<<<pg, 256, PROJ_SMEM>>>(key,   Wk, bk, kh, kl, 1, 1.0f);
    proj_mma<<<pg, 256, PROJ_SMEM>>>(value, Wv, bv, vh, vl, 2, 1.0f);

    dim3 ag(SEQ / 128, NHEAD, BBATCH);  // (16, 16, 4)
    attn_mma<<<ag, 256, ATTN_SMEM>>>(qh, ql, kh, kl, vh, vl, at);

    proj_mma<<<pg, 256, PROJ_SMEM>>>(at, Wo, bo, out, nullptr, 0, 1.0f);
}